// round 16
// baseline (speedup 1.0000x reference)
#include <cuda_runtime.h>
#include <math.h>
#include <stdint.h>

#define T_TOK 1024
#define DIM   2048
#define NH    32
#define NKV   4
#define HD    128
#define ROT   64
#define NE    8
#define MI    1408
#define SI    5632
#define S_LEN 512
#define MC    1024
#define EPS_F 1e-6f

// ---------------- device scratch ----------------
__device__ float g_h   [T_TOK * DIM];          // tf32-rounded, k-interleaved (GEMM A)
__device__ float g_xq  [T_TOK * NH * 256];
__device__ float g_xk  [T_TOK * NKV * HD];
__device__ float g_xv  [T_TOK * NKV * HD];
__device__ float g_ck  [2 * NKV * MC * HD];
__device__ float g_cv  [2 * NKV * MC * HD];
__device__ float g_scores[(size_t)64 * S_LEN * S_LEN];
__device__ float g_attn[T_TOK * NH * HD];      // k-interleaved (A of wo)
__device__ float g_x2  [T_TOK * DIM];
__device__ float g_hfr [T_TOK * DIM];          // rounded + k-interleaved (GEMM A)
__device__ int   g_cnt [NE];
__device__ int   g_list[NE * T_TOK];
__device__ int   g_texp[T_TOK * 2];
__device__ int   g_tslot[T_TOK * 2];
__device__ float g_tw  [T_TOK * 2];
__device__ float g_gu  [(size_t)NE * T_TOK * 2 * MI];
__device__ float g_act [(size_t)NE * T_TOK * MI];   // k-interleaved
__device__ float g_down[(size_t)NE * T_TOK * DIM];
__device__ float g_shg [(size_t)T_TOK * SI];
__device__ float g_shu [(size_t)T_TOK * SI];
__device__ float g_shh [(size_t)T_TOK * SI];        // k-interleaved
__device__ float g_shout[T_TOK * DIM];
__device__ float g_sg  [T_TOK];

// ---------------- helpers ----------------
__device__ __forceinline__ uint32_t f2tf32(float v) {
    uint32_t r; asm("cvt.rna.tf32.f32 %0, %1;" : "=r"(r) : "f"(v)); return r;
}
__device__ __forceinline__ float rnd_tf32(float v) {
    return __uint_as_float(f2tf32(v));
}
// interleave low 3 bits of index: pair (c, c+4) becomes adjacent (2c, 2c+1)
__device__ __forceinline__ int permk(int k) {
    return (k & ~7) | (((k & 3) << 1) | ((k >> 2) & 1));
}
__device__ __forceinline__ void mma_tf32(float* d, const uint32_t* a, const uint32_t* b) {
    asm volatile(
        "mma.sync.aligned.m16n8k8.row.col.f32.tf32.tf32.f32 "
        "{%0,%1,%2,%3}, {%4,%5,%6,%7}, {%8,%9}, {%0,%1,%2,%3};\n"
        : "+f"(d[0]), "+f"(d[1]), "+f"(d[2]), "+f"(d[3])
        : "r"(a[0]), "r"(a[1]), "r"(a[2]), "r"(a[3]), "r"(b[0]), "r"(b[1]));
}
__device__ __forceinline__ void cp16(uint32_t smem_addr, const void* gptr, int src_bytes) {
    asm volatile("cp.async.cg.shared.global [%0], [%1], 16, %2;\n"
                 :: "r"(smem_addr), "l"(gptr), "r"(src_bytes));
}
__device__ __forceinline__ void cp_commit() { asm volatile("cp.async.commit_group;\n"); }
__device__ __forceinline__ void cp_wait0()  { asm volatile("cp.async.wait_group 0;\n"); }
__device__ __forceinline__ void cp_wait1()  { asm volatile("cp.async.wait_group 1;\n"); }
__device__ __forceinline__ void cp_wait2()  { asm volatile("cp.async.wait_group 2;\n"); }
__device__ __forceinline__ float sigm(float v) { return 1.0f / (1.0f + expf(-v)); }

#define BSTRN 136    // [k][n] row stride (words)
#define BSTRT 20     // [n][k] (BT) row stride (words), conflict-free LDS32
#define STG_W 3072   // words per stage per array (max: 128*24)
#define NSTAGE 4
#define GEMM_SMEM_BYTES (NSTAGE * 2 * STG_W * 4)   // 98304 (96 KB)

// ---- tf32 GEMM: 128x128 tile, BK=16, 256 thr, 4-stage cp.async pipeline ----
// AIL: A is k-interleaved (permk) -> A-frags via LDS64, stride 24 (conflict-free).
// CVTB: round B fragments. EPI: 0=store, 1=+res, 2=atomicAdd, 3=rnd(acc*sigm(res))
//   with k-interleaved store positions (feeds wo as A).
template<bool BT, int EPI, bool CVTB, bool AIL>
__device__ __forceinline__ void gemm_cp(
    const float* __restrict__ A, int lda,
    const float* __restrict__ B, int ldb,
    float* __restrict__ C, int ldc,
    int M, int N, int kb, int ke,
    const int* __restrict__ gather,
    const float* __restrict__ res, int ldres)
{
    constexpr int ASTR = AIL ? 24 : 20;
    extern __shared__ __align__(16) float smem_dyn[];
    float* AsBase = smem_dyn;
    float* BsBase = smem_dyn + NSTAGE * STG_W;

    const int tid  = threadIdx.x;
    const int lane = tid & 31, wid = tid >> 5;
    const int m0 = blockIdx.y * 128, n0 = blockIdx.x * 128;
    if (m0 >= M) return;
    const int wm = (wid >> 2) * 64;
    const int wn = (wid & 3) * 32;

    float acc[16][4];
#pragma unroll
    for (int i = 0; i < 16; i++)
#pragma unroll
        for (int j = 0; j < 4; j++) acc[i][j] = 0.0f;

    const int am  = tid >> 1;
    const int akq = (tid & 1) * 8;
    const bool avalid = (m0 + am < M);
    const int arow = avalid ? (gather ? gather[m0 + am] : (m0 + am)) : 0;
    const float* aptr = A + (size_t)arow * lda + akq;
    const int asz = avalid ? 16 : 0;
    const uint32_t a_s = (uint32_t)__cvta_generic_to_shared(&AsBase[am * ASTR + akq]);

    const float* bptr;
    uint32_t b_s;
    if (!BT) {
        int bk_ = tid >> 4;
        int bn_ = (tid & 15) * 8;
        bptr = B + (size_t)bk_ * ldb + n0 + bn_;
        b_s = (uint32_t)__cvta_generic_to_shared(&BsBase[bk_ * BSTRN + bn_]);
    } else {
        int bn_ = tid >> 1;
        int bk_ = (tid & 1) * 8;
        bptr = B + (size_t)(n0 + bn_) * ldb + bk_;
        b_s = (uint32_t)__cvta_generic_to_shared(&BsBase[bn_ * BSTRT + bk_]);
    }

    auto issue = [&](int p, int k0) {
        uint32_t ad = a_s + p * (STG_W * 4);
        uint32_t bd = b_s + p * (STG_W * 4);
        cp16(ad,      aptr + k0,     asz);
        cp16(ad + 16, aptr + k0 + 4, asz);
        const float* bs = !BT ? (bptr + (size_t)k0 * ldb) : (bptr + k0);
        cp16(bd,      bs,     16);
        cp16(bd + 16, bs + 4, 16);
        cp_commit();
    };

    auto compute = [&](int p) {
        const uint32_t* As = (const uint32_t*)(AsBase + p * STG_W);
        const float*    Bs = BsBase + p * STG_W;
        const int r = lane >> 2, c = lane & 3;
#pragma unroll
        for (int ks = 0; ks < 2; ks++) {
            const int kbq = ks * 8;
            uint32_t af[4][4], bf[4][2];
#pragma unroll
            for (int mt = 0; mt < 4; mt++) {
                if (AIL) {
                    // interleaved: pos 2c holds k=c, pos 2c+1 holds k=c+4
                    const uint2* p0 = (const uint2*)&As[(wm + mt * 16 + r) * ASTR + kbq + 2 * c];
                    const uint2* p1 = (const uint2*)&As[(wm + mt * 16 + r + 8) * ASTR + kbq + 2 * c];
                    uint2 q0 = *p0, q1 = *p1;
                    af[mt][0] = q0.x; af[mt][2] = q0.y;
                    af[mt][1] = q1.x; af[mt][3] = q1.y;
                } else {
                    const uint32_t* ab = &As[(wm + mt * 16 + r) * ASTR + kbq + c];
                    af[mt][0] = ab[0];
                    af[mt][1] = ab[8 * ASTR];
                    af[mt][2] = ab[4];
                    af[mt][3] = ab[8 * ASTR + 4];
                }
            }
#pragma unroll
            for (int nt = 0; nt < 4; nt++) {
                float b0, b1;
                if (!BT) {
                    const float* bb = &Bs[(kbq + c) * BSTRN + wn + nt * 8 + r];
                    b0 = bb[0];
                    b1 = bb[4 * BSTRN];
                } else {
                    const float* bb = &Bs[(wn + nt * 8 + r) * BSTRT + kbq + c];
                    b0 = bb[0];
                    b1 = bb[4];
                }
                if (CVTB) { bf[nt][0] = f2tf32(b0); bf[nt][1] = f2tf32(b1); }
                else      { bf[nt][0] = __float_as_uint(b0); bf[nt][1] = __float_as_uint(b1); }
            }
#pragma unroll
            for (int mt = 0; mt < 4; mt++)
#pragma unroll
                for (int nt = 0; nt < 4; nt++)
                    mma_tf32(acc[mt * 4 + nt], af[mt], bf[nt]);
        }
    };

    issue(0, kb);
    if (kb + 16 < ke) issue(1, kb + 16);
    if (kb + 32 < ke) issue(2, kb + 32);
    int cur = 0;
    for (int k0 = kb; k0 < ke; k0 += 16) {
        int nrem = (ke - k0) >> 4;
        if (nrem >= 3) cp_wait2(); else if (nrem == 2) cp_wait1(); else cp_wait0();
        __syncthreads();
        if (k0 + 48 < ke) {
            int nx = cur + 3; if (nx >= NSTAGE) nx -= NSTAGE;
            issue(nx, k0 + 48);
        }
        compute(cur);
        if (++cur == NSTAGE) cur = 0;
    }

    // epilogue
    const int r = lane >> 2, c2 = (lane & 3) * 2;
#pragma unroll
    for (int mt = 0; mt < 4; mt++) {
#pragma unroll
        for (int nt = 0; nt < 4; nt++) {
            const float* a4 = acc[mt * 4 + nt];
            int row0 = m0 + wm + mt * 16 + r;
            int col  = n0 + wn + nt * 8 + c2;
            if (row0 < M) {
                float* cp_ = C + (size_t)row0 * ldc;
                if (EPI == 2) { atomicAdd(cp_ + col, a4[0]); atomicAdd(cp_ + col + 1, a4[1]); }
                else if (EPI == 3) {
                    cp_[permk(col)]     = rnd_tf32(a4[0] * sigm(res[(size_t)row0 * ldres + col]));
                    cp_[permk(col + 1)] = rnd_tf32(a4[1] * sigm(res[(size_t)row0 * ldres + col + 1]));
                } else {
                    float v0 = a4[0], v1 = a4[1];
                    if (EPI == 1) { v0 += res[(size_t)row0 * ldres + col];
                                    v1 += res[(size_t)row0 * ldres + col + 1]; }
                    cp_[col] = v0; cp_[col + 1] = v1;
                }
            }
            int row1 = row0 + 8;
            if (row1 < M) {
                float* cp_ = C + (size_t)row1 * ldc;
                if (EPI == 2) { atomicAdd(cp_ + col, a4[2]); atomicAdd(cp_ + col + 1, a4[3]); }
                else if (EPI == 3) {
                    cp_[permk(col)]     = rnd_tf32(a4[2] * sigm(res[(size_t)row1 * ldres + col]));
                    cp_[permk(col + 1)] = rnd_tf32(a4[3] * sigm(res[(size_t)row1 * ldres + col + 1]));
                } else {
                    float v2 = a4[2], v3 = a4[3];
                    if (EPI == 1) { v2 += res[(size_t)row1 * ldres + col];
                                    v3 += res[(size_t)row1 * ldres + col + 1]; }
                    cp_[col] = v2; cp_[col + 1] = v3;
                }
            }
        }
    }
}

// ---------------- GEMM wrappers ----------------
__global__ __launch_bounds__(256, 2) void k_gemm_wq(const float* A, const float* B, float* C) {
    gemm_cp<false, 0, true, true>(A, DIM, B, NH * 256, C, NH * 256, T_TOK, NH * 256, 0, DIM,
                                  nullptr, nullptr, 0);
}
__global__ __launch_bounds__(256, 2) void k_gemm_kv(const float* A,
                          const float* B0, const float* B1, float* C0, float* C1) {
    int sel = blockIdx.z & 1, kz = blockIdx.z >> 1;
    const float* B = sel ? B1 : B0;
    float* C = sel ? C1 : C0;
    gemm_cp<false, 2, true, true>(A, DIM, B, NKV * HD, C, NKV * HD, T_TOK, NKV * HD,
                                  kz * 512, kz * 512 + 512, nullptr, nullptr, 0);
}
__global__ __launch_bounds__(256, 2) void k_gemm_wo(const float* A, const float* B, float* C) {
    int kz = blockIdx.z;
    gemm_cp<false, 2, true, true>(A, NH * HD, B, DIM, C, DIM, T_TOK, DIM,
                                  kz * 1024, kz * 1024 + 1024, nullptr, nullptr, 0);
}
__global__ __launch_bounds__(256, 2) void k_scores(int b) {
    if (blockIdx.x > blockIdx.y) return;
    int h = blockIdx.z; int z = b * 32 + h;
    gemm_cp<true, 0, false, false>(g_xq + (size_t)b * S_LEN * (NH * 256) + h * 256, NH * 256,
                                   g_ck + (size_t)(b * NKV + (h >> 3)) * MC * HD, HD,
                                   g_scores + (size_t)z * S_LEN * S_LEN, S_LEN,
                                   S_LEN, S_LEN, 0, HD, nullptr, nullptr, 0);
}
__global__ __launch_bounds__(256, 2) void k_attnv(int b) {
    int h = blockIdx.z; int z = b * 32 + h;
    int K_eff = blockIdx.y * 128 + 128;
    gemm_cp<false, 3, false, false>(g_scores + (size_t)z * S_LEN * S_LEN, S_LEN,
                                    g_cv + (size_t)(b * NKV + (h >> 3)) * MC * HD, HD,
                                    g_attn + (size_t)b * S_LEN * (NH * HD) + h * HD, NH * HD,
                                    S_LEN, HD, 0, K_eff, nullptr,
                                    g_xq + (size_t)b * S_LEN * (NH * 256) + h * 256 + 128, NH * 256);
}
__global__ __launch_bounds__(256, 2) void k_moe_gu(const float* __restrict__ egu) {
    int e = blockIdx.z; int M = g_cnt[e];
    gemm_cp<true, 0, true, true>(g_hfr, DIM,
                                 egu + (size_t)e * 2 * MI * DIM, DIM,
                                 g_gu + (size_t)e * T_TOK * 2 * MI, 2 * MI,
                                 M, 2 * MI, 0, DIM, g_list + e * T_TOK, nullptr, 0);
}
__global__ __launch_bounds__(256, 2) void k_moe_down(const float* __restrict__ ed) {
    int e = blockIdx.z; int M = g_cnt[e];
    gemm_cp<true, 0, true, true>(g_act + (size_t)e * T_TOK * MI, MI,
                                 ed + (size_t)e * DIM * MI, MI,
                                 g_down + (size_t)e * T_TOK * DIM, DIM,
                                 M, DIM, 0, MI, nullptr, nullptr, 0);
}
__global__ __launch_bounds__(256, 2) void k_gemm_sh(const float* A,
                          const float* B0, const float* B1, float* C0, float* C1) {
    const float* B = blockIdx.z ? B1 : B0;
    float* C = blockIdx.z ? C1 : C0;
    gemm_cp<false, 0, true, true>(A, DIM, B, SI, C, SI, T_TOK, SI, 0, DIM, nullptr, nullptr, 0);
}
__global__ __launch_bounds__(256, 2) void k_gemm_shd(const float* A, const float* B, float* C) {
    int kz = blockIdx.z;
    gemm_cp<false, 2, true, true>(A, SI, B, DIM, C, DIM, T_TOK, DIM,
                                  kz * 1408, kz * 1408 + 1408, nullptr, nullptr, 0);
}

// ---------------- elementwise / norm / softmax kernels ----------------
__global__ void k_zero_cnt() { if (threadIdx.x < NE) g_cnt[threadIdx.x] = 0; }

// rmsnorm; out_round is k-interleaved. If rw != nullptr also computes router
// top-2 + token lists + shared-expert sigmoid gate from exact in-register values.
__global__ void k_rmsnorm(const float* __restrict__ in, const float* __restrict__ w,
                          float* __restrict__ out_round,
                          const float* __restrict__ rw, const float* __restrict__ segw) {
    int t = blockIdx.x; int tid = threadIdx.x;
    const float* r = in + (size_t)t * DIM;
    float xv[8];
    float ss = 0.f;
#pragma unroll
    for (int j = 0; j < 8; j++) {
        float v = r[tid + j * 256];
        xv[j] = v;
        ss += v * v;
    }
    __shared__ float sm[256];
    sm[tid] = ss; __syncthreads();
    for (int o = 128; o > 0; o >>= 1) { if (tid < o) sm[tid] += sm[tid + o]; __syncthreads(); }
    float rinv = rsqrtf(sm[0] * (1.0f / DIM) + EPS_F);
    const int pd = permk(tid) & 7;            // tid<256, d&7 == tid&7
    float hv[8];
#pragma unroll
    for (int j = 0; j < 8; j++) {
        int d = tid + j * 256;
        hv[j] = xv[j] * rinv * (1.0f + w[d]);
        out_round[(size_t)t * DIM + ((d & ~7) | pd)] = rnd_tf32(hv[j]);
    }
    if (rw == nullptr) return;

    float loc[NE];
#pragma unroll
    for (int e = 0; e < NE; e++) loc[e] = 0.f;
    float segacc = 0.f;
#pragma unroll
    for (int j = 0; j < 8; j++) {
        int d = tid + j * 256;
        float h = hv[j];
#pragma unroll
        for (int e = 0; e < NE; e++) loc[e] += h * rw[e * DIM + d];
        segacc += h * segw[d];
    }
    __shared__ float logits[NE];
    __syncthreads();
    for (int e = 0; e < NE; e++) {
        sm[tid] = loc[e]; __syncthreads();
        for (int o = 128; o > 0; o >>= 1) { if (tid < o) sm[tid] += sm[tid + o]; __syncthreads(); }
        if (tid == 0) logits[e] = sm[0];
        __syncthreads();
    }
    sm[tid] = segacc; __syncthreads();
    for (int o = 128; o > 0; o >>= 1) { if (tid < o) sm[tid] += sm[tid + o]; __syncthreads(); }
    if (tid == 0) {
        g_sg[t] = sigm(sm[0]);
        float mx = logits[0];
        for (int e = 1; e < NE; e++) mx = fmaxf(mx, logits[e]);
        float pe[NE]; float s = 0.f;
        for (int e = 0; e < NE; e++) { pe[e] = expf(logits[e] - mx); s += pe[e]; }
        for (int e = 0; e < NE; e++) pe[e] /= s;
        int i0 = 0; float v0 = pe[0];
        for (int e = 1; e < NE; e++) if (pe[e] > v0) { v0 = pe[e]; i0 = e; }
        int i1 = -1; float v1 = -1.f;
        for (int e = 0; e < NE; e++) if (e != i0 && pe[e] > v1) { v1 = pe[e]; i1 = e; }
        float wsum = v0 + v1;
        int s0 = atomicAdd(&g_cnt[i0], 1); g_list[i0 * T_TOK + s0] = t;
        int s1 = atomicAdd(&g_cnt[i1], 1); g_list[i1 * T_TOK + s1] = t;
        g_texp[t * 2] = i0;  g_tslot[t * 2] = s0;  g_tw[t * 2] = v0 / wsum;
        g_texp[t * 2 + 1] = i1; g_tslot[t * 2 + 1] = s1; g_tw[t * 2 + 1] = v1 / wsum;
    }
}

// warp-per-head rope: lane holds float4 (4 consecutive d); pairs are lane-local.
__device__ __forceinline__ float4 rope_vec(float4 v, int lane, int pos,
                                           const float* __restrict__ nw,
                                           const float* __restrict__ fc) {
    float ss = v.x * v.x + v.y * v.y + v.z * v.z + v.w * v.w;
#pragma unroll
    for (int o = 16; o > 0; o >>= 1) ss += __shfl_xor_sync(0xffffffffu, ss, o);
    float rinv = rsqrtf(ss * (1.0f / HD) + EPS_F);
    const float4 nwv = *(const float4*)(nw + lane * 4);
    float x0 = v.x * rinv * (1.0f + nwv.x);
    float x1 = v.y * rinv * (1.0f + nwv.y);
    float x2 = v.z * rinv * (1.0f + nwv.z);
    float x3 = v.w * rinv * (1.0f + nwv.w);
    float4 o;
    if (lane < 16) {
        int i0 = lane * 2, i1 = lane * 2 + 1;
        float c0 = fc[((size_t)pos * 32 + i0) * 2 + 0];
        float s0 = fc[((size_t)pos * 32 + i0) * 2 + 1];
        float c1 = fc[((size_t)pos * 32 + i1) * 2 + 0];
        float s1 = fc[((size_t)pos * 32 + i1) * 2 + 1];
        o.x = x0 * c0 - x1 * s0;
        o.y = x0 * s0 + x1 * c0;
        o.z = x2 * c1 - x3 * s1;
        o.w = x2 * s1 + x3 * c1;
    } else { o.x = x0; o.y = x1; o.z = x2; o.w = x3; }
    o.x = rnd_tf32(o.x); o.y = rnd_tf32(o.y); o.z = rnd_tf32(o.z); o.w = rnd_tf32(o.w);
    return o;
}

__global__ void k_rope_q(const float* __restrict__ qn, const float* __restrict__ fc,
                         const int* __restrict__ seqpos) {
    int idx = blockIdx.x * 8 + (threadIdx.x >> 5);
    int lane = threadIdx.x & 31;
    int t = idx >> 5, h = idx & 31;
    int b = t >> 9, s = t & 511;
    float4* base = (float4*)(g_xq + (size_t)t * (NH * 256) + h * 256) + lane;
    float4 v = *base;
    *base = rope_vec(v, lane, seqpos[b] + s, qn, fc);
}

__global__ void k_rope_k(const float* __restrict__ kn, const float* __restrict__ fc,
                         const int* __restrict__ seqpos) {
    int idx = blockIdx.x * 8 + (threadIdx.x >> 5);
    int lane = threadIdx.x & 31;
    int t = idx >> 2, h = idx & 3;
    int b = t >> 9, s = t & 511;
    float4 v = *((const float4*)(g_xk + (size_t)t * (NKV * HD) + h * HD) + lane);
    int pos = seqpos[b] + s;
    float4 o = rope_vec(v, lane, pos, kn, fc);
    *((float4*)(g_ck + (((size_t)(b * NKV + h)) * MC + pos) * HD) + lane) = o;
}

__global__ void k_scatter_v(const int* __restrict__ seqpos) {
    int i = blockIdx.x * 256 + threadIdx.x;
    int t = i >> 7, rem = i & 127;
    int h = rem >> 5, d4 = rem & 31;
    int b = t >> 9, s = t & 511;
    int pos = seqpos[b] + s;
    float4 v = *((const float4*)(g_xv + (size_t)t * (NKV * HD) + h * HD) + d4);
    v.x = rnd_tf32(v.x); v.y = rnd_tf32(v.y); v.z = rnd_tf32(v.z); v.w = rnd_tf32(v.w);
    *((float4*)(g_cv + (((size_t)(b * NKV + h)) * MC + pos) * HD) + d4) = v;
}

__global__ void k_softmax(int b) {
    int q = blockIdx.x; int z = b * 32 + blockIdx.y;
    float* row = g_scores + ((size_t)z * S_LEN + q) * S_LEN;
    int tid = threadIdx.x;
    const float scale = 0.08838834764831845f;
    float vals[4];
    float m = -1e30f;
#pragma unroll
    for (int j = 0; j < 4; j++) {
        int c = tid + j * 128;
        float sv = (c <= q) ? row[c] * scale : -1e30f;
        vals[j] = sv;
        if (sv > m) m = sv;
    }
    __shared__ float red[4];
#pragma unroll
    for (int o = 16; o > 0; o >>= 1) m = fmaxf(m, __shfl_xor_sync(0xffffffffu, m, o));
    if ((tid & 31) == 0) red[tid >> 5] = m;
    __syncthreads();
    m = fmaxf(fmaxf(red[0], red[1]), fmaxf(red[2], red[3]));
    __syncthreads();
    float p[4]; float sum = 0.f;
#pragma unroll
    for (int j = 0; j < 4; j++) {
        int c = tid + j * 128;
        p[j] = (c <= q) ? expf(vals[j] - m) : 0.0f;
        sum += p[j];
    }
#pragma unroll
    for (int o = 16; o > 0; o >>= 1) sum += __shfl_xor_sync(0xffffffffu, sum, o);
    if ((tid & 31) == 0) red[tid >> 5] = sum;
    __syncthreads();
    sum = red[0] + red[1] + red[2] + red[3];
    float inv = 1.0f / sum;
#pragma unroll
    for (int j = 0; j < 4; j++) row[tid + j * 128] = rnd_tf32(p[j] * inv);
}

__global__ void k_moe_silu() {
    int e = blockIdx.y;
    int idx = blockIdx.x * 256 + threadIdx.x;
    int rM = g_cnt[e];
    int rr = idx / MI, c = idx - rr * MI;
    if (rr >= rM) return;
    const float* gu = g_gu + ((size_t)e * T_TOK + rr) * 2 * MI;
    float gvv = gu[c], u = gu[MI + c];
    g_act[((size_t)e * T_TOK + rr) * MI + permk(c)] = rnd_tf32(gvv / (1.0f + expf(-gvv)) * u);
}

__global__ void k_sh_silu() {
    size_t idx = (size_t)blockIdx.x * 256 + threadIdx.x;
    float gvv = g_shg[idx];
    // SI % 8 == 0 so permuting low 3 bits stays within the row's k-dim
    size_t widx = (idx & ~(size_t)7) | (size_t)(permk((int)(idx & 7)));
    g_shh[widx] = rnd_tf32(gvv / (1.0f + expf(-gvv)) * g_shu[idx]);
}

__global__ void k_final(const float* __restrict__ x_res, float* __restrict__ out) {
    size_t idx = (size_t)blockIdx.x * 256 + threadIdx.x;
    int t = (int)(idx >> 11);
    int e0 = g_texp[t * 2], e1 = g_texp[t * 2 + 1];
    int s0 = g_tslot[t * 2], s1 = g_tslot[t * 2 + 1];
    int d = (int)(idx & 2047);
    float moe = g_tw[t * 2]     * g_down[((size_t)e0 * T_TOK + s0) * DIM + d]
              + g_tw[t * 2 + 1] * g_down[((size_t)e1 * T_TOK + s1) * DIM + d];
    out[idx] = g_x2[idx] + moe + g_shout[idx] * g_sg[t];
}

// ---------------- launch ----------------
extern "C" void kernel_launch(void* const* d_in, const int* in_sizes, int n_in,
                              void* d_out, int out_size) {
    const float* x    = (const float*)d_in[0];
    const float* fc   = (const float*)d_in[1];
    const float* cin_k = (const float*)d_in[2];
    const float* cin_v = (const float*)d_in[3];
    const int*   seqpos = (const int*)d_in[4];
    const float* wq   = (const float*)d_in[6];
    const float* wk   = (const float*)d_in[7];
    const float* wv   = (const float*)d_in[8];
    const float* wo   = (const float*)d_in[9];
    const float* q_norm = (const float*)d_in[10];
    const float* k_norm = (const float*)d_in[11];
    const float* anw  = (const float*)d_in[12];
    const float* fnw  = (const float*)d_in[13];
    const float* rw   = (const float*)d_in[14];
    const float* egu  = (const float*)d_in[15];
    const float* ed   = (const float*)d_in[16];
    const float* shg  = (const float*)d_in[17];
    const float* shu  = (const float*)d_in[18];
    const float* shd  = (const float*)d_in[19];
    const float* seg  = (const float*)d_in[20];

    float* out = (float*)d_out;
    const size_t OUT_ELEMS = (size_t)2 * S_LEN * DIM;
    const size_t CK_ELEMS  = (size_t)2 * NKV * MC * HD;

    float *p_h, *p_xq, *p_xk, *p_xv, *p_attn, *p_x2, *p_hfr,
          *p_shgb, *p_shub, *p_shhb, *p_shoutb, *p_ck, *p_cv;
    cudaGetSymbolAddress((void**)&p_h,    g_h);
    cudaGetSymbolAddress((void**)&p_xq,   g_xq);
    cudaGetSymbolAddress((void**)&p_xk,   g_xk);
    cudaGetSymbolAddress((void**)&p_xv,   g_xv);
    cudaGetSymbolAddress((void**)&p_attn, g_attn);
    cudaGetSymbolAddress((void**)&p_x2,   g_x2);
    cudaGetSymbolAddress((void**)&p_hfr,  g_hfr);
    cudaGetSymbolAddress((void**)&p_shgb, g_shg);
    cudaGetSymbolAddress((void**)&p_shub, g_shu);
    cudaGetSymbolAddress((void**)&p_shhb, g_shh);
    cudaGetSymbolAddress((void**)&p_shoutb, g_shout);
    cudaGetSymbolAddress((void**)&p_ck,   g_ck);
    cudaGetSymbolAddress((void**)&p_cv,   g_cv);

    static bool init_done = false;
    static cudaStream_t s1, s2;
    static cudaEvent_t ev_fork0, ev_rms1, ev_ropeq, ev_kvdone, ev_attn1,
                       ev_rms2, ev_sh, ev_cache;
    if (!init_done) {
        cudaFuncSetAttribute(k_gemm_wq,   cudaFuncAttributeMaxDynamicSharedMemorySize, GEMM_SMEM_BYTES);
        cudaFuncSetAttribute(k_gemm_kv,   cudaFuncAttributeMaxDynamicSharedMemorySize, GEMM_SMEM_BYTES);
        cudaFuncSetAttribute(k_gemm_wo,   cudaFuncAttributeMaxDynamicSharedMemorySize, GEMM_SMEM_BYTES);
        cudaFuncSetAttribute(k_scores,    cudaFuncAttributeMaxDynamicSharedMemorySize, GEMM_SMEM_BYTES);
        cudaFuncSetAttribute(k_attnv,     cudaFuncAttributeMaxDynamicSharedMemorySize, GEMM_SMEM_BYTES);
        cudaFuncSetAttribute(k_moe_gu,    cudaFuncAttributeMaxDynamicSharedMemorySize, GEMM_SMEM_BYTES);
        cudaFuncSetAttribute(k_moe_down,  cudaFuncAttributeMaxDynamicSharedMemorySize, GEMM_SMEM_BYTES);
        cudaFuncSetAttribute(k_gemm_sh,   cudaFuncAttributeMaxDynamicSharedMemorySize, GEMM_SMEM_BYTES);
        cudaFuncSetAttribute(k_gemm_shd,  cudaFuncAttributeMaxDynamicSharedMemorySize, GEMM_SMEM_BYTES);
        cudaStreamCreateWithFlags(&s1, cudaStreamNonBlocking);
        cudaStreamCreateWithFlags(&s2, cudaStreamNonBlocking);
        cudaEventCreateWithFlags(&ev_fork0,  cudaEventDisableTiming);
        cudaEventCreateWithFlags(&ev_rms1,   cudaEventDisableTiming);
        cudaEventCreateWithFlags(&ev_ropeq,  cudaEventDisableTiming);
        cudaEventCreateWithFlags(&ev_kvdone, cudaEventDisableTiming);
        cudaEventCreateWithFlags(&ev_attn1,  cudaEventDisableTiming);
        cudaEventCreateWithFlags(&ev_rms2,   cudaEventDisableTiming);
        cudaEventCreateWithFlags(&ev_sh,     cudaEventDisableTiming);
        cudaEventCreateWithFlags(&ev_cache,  cudaEventDisableTiming);
        init_done = true;
    }

    // ---- fork side streams at the start ----
    cudaEventRecord(ev_fork0, 0);
    cudaStreamWaitEvent(s1, ev_fork0, 0);
    cudaStreamWaitEvent(s2, ev_fork0, 0);

    // s1: cache seeds + kv accumulator zeroing
    cudaMemcpyAsync(p_ck, cin_k, CK_ELEMS * sizeof(float), cudaMemcpyDeviceToDevice, s1);
    cudaMemcpyAsync(p_cv, cin_v, CK_ELEMS * sizeof(float), cudaMemcpyDeviceToDevice, s1);
    cudaMemsetAsync(p_xk, 0, (size_t)T_TOK * NKV * HD * sizeof(float), s1);
    cudaMemsetAsync(p_xv, 0, (size_t)T_TOK * NKV * HD * sizeof(float), s1);
    // s2: split-K inits
    cudaMemsetAsync(p_shoutb, 0, (size_t)T_TOK * DIM * sizeof(float), s2);
    cudaMemcpyAsync(p_x2, x, (size_t)T_TOK * DIM * sizeof(float), cudaMemcpyDeviceToDevice, s2);

    // default: rmsnorm1 (+ router counter zero)
    k_zero_cnt<<<1, 32>>>();
    k_rmsnorm<<<T_TOK, 256>>>(x, anw, p_h, nullptr, nullptr);
    cudaEventRecord(ev_rms1, 0);

    // default: wq chain
    k_gemm_wq<<<dim3(64, 8), 256, GEMM_SMEM_BYTES>>>(p_h, wq, p_xq);
    k_rope_q<<<(T_TOK * NH) / 8, 256>>>(q_norm, fc, seqpos);
    cudaEventRecord(ev_ropeq, 0);

    // s1: kv chain
    cudaStreamWaitEvent(s1, ev_rms1, 0);
    k_gemm_kv<<<dim3(4, 8, 8), 256, GEMM_SMEM_BYTES, s1>>>(p_h, wk, wv, p_xk, p_xv);
    k_rope_k<<<(T_TOK * NKV) / 8, 256, 0, s1>>>(k_norm, fc, seqpos);
    k_scatter_v<<<(T_TOK * 128) / 256, 256, 0, s1>>>(seqpos);
    cudaEventRecord(ev_kvdone, s1);

    // s2: stream caches out
    cudaStreamWaitEvent(s2, ev_kvdone, 0);
    if ((size_t)out_size >= OUT_ELEMS + 2 * CK_ELEMS) {
        cudaMemcpyAsync(out + OUT_ELEMS, p_ck, CK_ELEMS * sizeof(float),
                        cudaMemcpyDeviceToDevice, s2);
        cudaMemcpyAsync(out + OUT_ELEMS + CK_ELEMS, p_cv, CK_ELEMS * sizeof(float),
                        cudaMemcpyDeviceToDevice, s2);
    }
    cudaEventRecord(ev_cache, s2);

    // attention: batch 0 default, batch 1 s1 (gate fused into attnv)
    cudaStreamWaitEvent(0, ev_kvdone, 0);
    k_scores<<<dim3(4, 4, 32), 256, GEMM_SMEM_BYTES>>>(0);
    k_softmax<<<dim3(S_LEN, 32), 128>>>(0);
    k_attnv<<<dim3(1, 4, 32), 256, GEMM_SMEM_BYTES>>>(0);

    cudaStreamWaitEvent(s1, ev_ropeq, 0);
    k_scores<<<dim3(4, 4, 32), 256, GEMM_SMEM_BYTES, s1>>>(1);
    k_softmax<<<dim3(S_LEN, 32), 128, 0, s1>>>(1);
    k_attnv<<<dim3(1, 4, 32), 256, GEMM_SMEM_BYTES, s1>>>(1);
    cudaEventRecord(ev_attn1, s1);

    // default: wo + fused rmsnorm2/router/seg
    cudaStreamWaitEvent(0, ev_attn1, 0);
    k_gemm_wo<<<dim3(16, 8, 4), 256, GEMM_SMEM_BYTES>>>(p_attn, wo, p_x2);
    k_rmsnorm<<<T_TOK, 256>>>(p_x2, fnw, p_hfr, rw, seg);
    cudaEventRecord(ev_rms2, 0);

    // default: MoE chain
    k_moe_gu<<<dim3(22, 8, 8), 256, GEMM_SMEM_BYTES>>>(egu);
    k_moe_silu<<<dim3((T_TOK * MI) / 256, 8), 256>>>();
    k_moe_down<<<dim3(16, 8, 8), 256, GEMM_SMEM_BYTES>>>(ed);

    // s1: shared-expert chain concurrent with MoE
    cudaStreamWaitEvent(s1, ev_rms2, 0);
    k_gemm_sh<<<dim3(44, 8, 2), 256, GEMM_SMEM_BYTES, s1>>>(p_hfr, shg, shu, p_shgb, p_shub);
    k_sh_silu<<<(int)(((size_t)T_TOK * SI) / 256), 256, 0, s1>>>();
    k_gemm_shd<<<dim3(16, 8, 4), 256, GEMM_SMEM_BYTES, s1>>>(p_shhb, shd, p_shoutb);
    cudaEventRecord(ev_sh, s1);

    // join + final combine
    cudaStreamWaitEvent(0, ev_sh, 0);
    cudaStreamWaitEvent(0, ev_cache, 0);
    k_final<<<(T_TOK * DIM) / 256, 256>>>(x, out);
}

// round 17
// speedup vs baseline: 1.0484x; 1.0484x over previous
#include <cuda_runtime.h>
#include <math.h>
#include <stdint.h>

#define T_TOK 1024
#define DIM   2048
#define NH    32
#define NKV   4
#define HD    128
#define ROT   64
#define NE    8
#define MI    1408
#define SI    5632
#define S_LEN 512
#define MC    1024
#define EPS_F 1e-6f

// ---------------- device scratch ----------------
__device__ float g_h   [T_TOK * DIM];          // tf32-rounded (GEMM A)
__device__ float g_xq  [T_TOK * NH * 256];
__device__ float g_xk  [T_TOK * NKV * HD];
__device__ float g_xv  [T_TOK * NKV * HD];
__device__ float g_ck  [2 * NKV * MC * HD];
__device__ float g_cv  [2 * NKV * MC * HD];
__device__ float g_scores[(size_t)64 * S_LEN * S_LEN];
__device__ float g_attn[T_TOK * NH * HD];
__device__ float g_x2  [T_TOK * DIM];
__device__ float g_hf  [T_TOK * DIM];          // exact (router/seg)
__device__ float g_hfr [T_TOK * DIM];          // rounded (GEMM A)
__device__ int   g_cnt [NE];
__device__ int   g_list[NE * T_TOK];
__device__ int   g_texp[T_TOK * 2];
__device__ int   g_tslot[T_TOK * 2];
__device__ float g_tw  [T_TOK * 2];
__device__ float g_gu  [(size_t)NE * T_TOK * 2 * MI];
__device__ float g_act [(size_t)NE * T_TOK * MI];
__device__ float g_down[(size_t)NE * T_TOK * DIM];
__device__ float g_shg [(size_t)T_TOK * SI];
__device__ float g_shu [(size_t)T_TOK * SI];
__device__ float g_shh [(size_t)T_TOK * SI];
__device__ float g_shout[T_TOK * DIM];
__device__ float g_sg  [T_TOK];

// ---------------- helpers ----------------
__device__ __forceinline__ uint32_t f2tf32(float v) {
    uint32_t r; asm("cvt.rna.tf32.f32 %0, %1;" : "=r"(r) : "f"(v)); return r;
}
__device__ __forceinline__ float rnd_tf32(float v) {
    return __uint_as_float(f2tf32(v));
}
__device__ __forceinline__ void mma_tf32(float* d, const uint32_t* a, const uint32_t* b) {
    asm volatile(
        "mma.sync.aligned.m16n8k8.row.col.f32.tf32.tf32.f32 "
        "{%0,%1,%2,%3}, {%4,%5,%6,%7}, {%8,%9}, {%0,%1,%2,%3};\n"
        : "+f"(d[0]), "+f"(d[1]), "+f"(d[2]), "+f"(d[3])
        : "r"(a[0]), "r"(a[1]), "r"(a[2]), "r"(a[3]), "r"(b[0]), "r"(b[1]));
}
__device__ __forceinline__ void cp16(uint32_t smem_addr, const void* gptr, int src_bytes) {
    asm volatile("cp.async.cg.shared.global [%0], [%1], 16, %2;\n"
                 :: "r"(smem_addr), "l"(gptr), "r"(src_bytes));
}
__device__ __forceinline__ void cp_commit() { asm volatile("cp.async.commit_group;\n"); }
__device__ __forceinline__ void cp_wait0()  { asm volatile("cp.async.wait_group 0;\n"); }
__device__ __forceinline__ void cp_wait1()  { asm volatile("cp.async.wait_group 1;\n"); }
__device__ __forceinline__ void cp_wait2()  { asm volatile("cp.async.wait_group 2;\n"); }
__device__ __forceinline__ float sigm(float v) { return 1.0f / (1.0f + expf(-v)); }

#define ASTR2 20     // [m][k] row stride (words): conflict-free
#define BSTRN 136    // [k][n] row stride (words)
#define STG_W 2560
#define NSTAGE 4
#define GEMM_SMEM_BYTES (NSTAGE * 2 * STG_W * 4)   // 81920

// ---- tf32 GEMM: 128x128 tile, BK=16, 256 thr, 4-stage cp.async pipeline ----
// A pre-rounded to tf32. CVTB: round B fragments (raw fp32 weights).
// EPI: 0=store, 1=+res, 2=atomicAdd (split-K), 3=store rnd_tf32(acc*sigmoid(res)).
template<bool BT, int EPI, bool CVTB>
__device__ __forceinline__ void gemm_cp(
    const float* __restrict__ A, int lda,
    const float* __restrict__ B, int ldb,
    float* __restrict__ C, int ldc,
    int M, int N, int kb, int ke,
    const int* __restrict__ gather,
    const float* __restrict__ res, int ldres)
{
    extern __shared__ __align__(16) float smem_dyn[];
    float* AsBase = smem_dyn;
    float* BsBase = smem_dyn + NSTAGE * STG_W;

    const int tid  = threadIdx.x;
    const int lane = tid & 31, wid = tid >> 5;
    const int m0 = blockIdx.y * 128, n0 = blockIdx.x * 128;
    if (m0 >= M) return;
    const int wm = (wid >> 2) * 64;
    const int wn = (wid & 3) * 32;

    float acc[16][4];
#pragma unroll
    for (int i = 0; i < 16; i++)
#pragma unroll
        for (int j = 0; j < 4; j++) acc[i][j] = 0.0f;

    const int am  = tid >> 1;
    const int akq = (tid & 1) * 8;
    const bool avalid = (m0 + am < M);
    const int arow = avalid ? (gather ? gather[m0 + am] : (m0 + am)) : 0;
    const float* aptr = A + (size_t)arow * lda + akq;
    const int asz = avalid ? 16 : 0;
    const uint32_t a_s = (uint32_t)__cvta_generic_to_shared(&AsBase[am * ASTR2 + akq]);

    const float* bptr;
    uint32_t b_s;
    if (!BT) {
        int bk_ = tid >> 4;
        int bn_ = (tid & 15) * 8;
        bptr = B + (size_t)bk_ * ldb + n0 + bn_;
        b_s = (uint32_t)__cvta_generic_to_shared(&BsBase[bk_ * BSTRN + bn_]);
    } else {
        int bn_ = tid >> 1;
        int bk_ = (tid & 1) * 8;
        bptr = B + (size_t)(n0 + bn_) * ldb + bk_;
        b_s = (uint32_t)__cvta_generic_to_shared(&BsBase[bn_ * ASTR2 + bk_]);
    }

    auto issue = [&](int p, int k0) {
        uint32_t ad = a_s + p * (STG_W * 4);
        uint32_t bd = b_s + p * (STG_W * 4);
        cp16(ad,      aptr + k0,     asz);
        cp16(ad + 16, aptr + k0 + 4, asz);
        const float* bs = !BT ? (bptr + (size_t)k0 * ldb) : (bptr + k0);
        cp16(bd,      bs,     16);
        cp16(bd + 16, bs + 4, 16);
        cp_commit();
    };

    auto compute = [&](int p) {
        const uint32_t* As = (const uint32_t*)(AsBase + p * STG_W);
        const float*    Bs = BsBase + p * STG_W;
        const int r = lane >> 2, c = lane & 3;
#pragma unroll
        for (int ks = 0; ks < 2; ks++) {
            const int kbq = ks * 8;
            uint32_t af[4][4], bf[4][2];
#pragma unroll
            for (int mt = 0; mt < 4; mt++) {
                const uint32_t* ab = &As[(wm + mt * 16 + r) * ASTR2 + kbq + c];
                af[mt][0] = ab[0];
                af[mt][1] = ab[8 * ASTR2];
                af[mt][2] = ab[4];
                af[mt][3] = ab[8 * ASTR2 + 4];
            }
#pragma unroll
            for (int nt = 0; nt < 4; nt++) {
                float b0, b1;
                if (!BT) {
                    const float* bb = &Bs[(kbq + c) * BSTRN + wn + nt * 8 + r];
                    b0 = bb[0];
                    b1 = bb[4 * BSTRN];
                } else {
                    const float* bb = &Bs[(wn + nt * 8 + r) * ASTR2 + kbq + c];
                    b0 = bb[0];
                    b1 = bb[4];
                }
                if (CVTB) { bf[nt][0] = f2tf32(b0); bf[nt][1] = f2tf32(b1); }
                else      { bf[nt][0] = __float_as_uint(b0); bf[nt][1] = __float_as_uint(b1); }
            }
#pragma unroll
            for (int mt = 0; mt < 4; mt++)
#pragma unroll
                for (int nt = 0; nt < 4; nt++)
                    mma_tf32(acc[mt * 4 + nt], af[mt], bf[nt]);
        }
    };

    issue(0, kb);
    if (kb + 16 < ke) issue(1, kb + 16);
    if (kb + 32 < ke) issue(2, kb + 32);
    int cur = 0;
    for (int k0 = kb; k0 < ke; k0 += 16) {
        int nrem = (ke - k0) >> 4;
        if (nrem >= 3) cp_wait2(); else if (nrem == 2) cp_wait1(); else cp_wait0();
        __syncthreads();
        if (k0 + 48 < ke) {
            int nx = cur + 3; if (nx >= NSTAGE) nx -= NSTAGE;
            issue(nx, k0 + 48);
        }
        compute(cur);
        if (++cur == NSTAGE) cur = 0;
    }

    // epilogue
    const int r = lane >> 2, c2 = (lane & 3) * 2;
#pragma unroll
    for (int mt = 0; mt < 4; mt++) {
#pragma unroll
        for (int nt = 0; nt < 4; nt++) {
            const float* a4 = acc[mt * 4 + nt];
            int row0 = m0 + wm + mt * 16 + r;
            int col  = n0 + wn + nt * 8 + c2;
            if (row0 < M) {
                float* cp_ = C + (size_t)row0 * ldc + col;
                if (EPI == 2) { atomicAdd(cp_, a4[0]); atomicAdd(cp_ + 1, a4[1]); }
                else if (EPI == 3) {
                    cp_[0] = rnd_tf32(a4[0] * sigm(res[(size_t)row0 * ldres + col]));
                    cp_[1] = rnd_tf32(a4[1] * sigm(res[(size_t)row0 * ldres + col + 1]));
                } else {
                    float v0 = a4[0], v1 = a4[1];
                    if (EPI == 1) { v0 += res[(size_t)row0 * ldres + col];
                                    v1 += res[(size_t)row0 * ldres + col + 1]; }
                    cp_[0] = v0; cp_[1] = v1;
                }
            }
            int row1 = row0 + 8;
            if (row1 < M) {
                float* cp_ = C + (size_t)row1 * ldc + col;
                if (EPI == 2) { atomicAdd(cp_, a4[2]); atomicAdd(cp_ + 1, a4[3]); }
                else if (EPI == 3) {
                    cp_[0] = rnd_tf32(a4[2] * sigm(res[(size_t)row1 * ldres + col]));
                    cp_[1] = rnd_tf32(a4[3] * sigm(res[(size_t)row1 * ldres + col + 1]));
                } else {
                    float v2 = a4[2], v3 = a4[3];
                    if (EPI == 1) { v2 += res[(size_t)row1 * ldres + col];
                                    v3 += res[(size_t)row1 * ldres + col + 1]; }
                    cp_[0] = v2; cp_[1] = v3;
                }
            }
        }
    }
}

// ---------------- GEMM wrappers ----------------
// wq half: M=512 rows starting at the given pointers (batch split)
__global__ __launch_bounds__(256, 2) void k_gemm_wq(const float* A, const float* B, float* C) {
    gemm_cp<false, 0, true>(A, DIM, B, NH * 256, C, NH * 256, S_LEN, NH * 256, 0, DIM,
                            nullptr, nullptr, 0);
}
__global__ __launch_bounds__(256, 2) void k_gemm_kv(const float* A,
                          const float* B0, const float* B1, float* C0, float* C1) {
    int sel = blockIdx.z & 1, kz = blockIdx.z >> 1;
    const float* B = sel ? B1 : B0;
    float* C = sel ? C1 : C0;
    gemm_cp<false, 2, true>(A, DIM, B, NKV * HD, C, NKV * HD, T_TOK, NKV * HD,
                            kz * 512, kz * 512 + 512, nullptr, nullptr, 0);
}
__global__ __launch_bounds__(256, 2) void k_gemm_wo(const float* A, const float* B, float* C) {
    int kz = blockIdx.z;
    gemm_cp<false, 2, true>(A, NH * HD, B, DIM, C, DIM, T_TOK, DIM,
                            kz * 1024, kz * 1024 + 1024, nullptr, nullptr, 0);
}
__global__ __launch_bounds__(256, 2) void k_scores(int b) {
    if (blockIdx.x > blockIdx.y) return;
    int h = blockIdx.z; int z = b * 32 + h;
    gemm_cp<true, 0, false>(g_xq + (size_t)b * S_LEN * (NH * 256) + h * 256, NH * 256,
                            g_ck + (size_t)(b * NKV + (h >> 3)) * MC * HD, HD,
                            g_scores + (size_t)z * S_LEN * S_LEN, S_LEN,
                            S_LEN, S_LEN, 0, HD, nullptr, nullptr, 0);
}
__global__ __launch_bounds__(256, 2) void k_attnv(int b) {
    int h = blockIdx.z; int z = b * 32 + h;
    int K_eff = blockIdx.y * 128 + 128;
    gemm_cp<false, 3, false>(g_scores + (size_t)z * S_LEN * S_LEN, S_LEN,
                             g_cv + (size_t)(b * NKV + (h >> 3)) * MC * HD, HD,
                             g_attn + (size_t)b * S_LEN * (NH * HD) + h * HD, NH * HD,
                             S_LEN, HD, 0, K_eff, nullptr,
                             g_xq + (size_t)b * S_LEN * (NH * 256) + h * 256 + 128, NH * 256);
}
__global__ __launch_bounds__(256, 2) void k_moe_gu(const float* __restrict__ egu) {
    int e = blockIdx.z; int M = g_cnt[e];
    gemm_cp<true, 0, true>(g_hfr, DIM,
                           egu + (size_t)e * 2 * MI * DIM, DIM,
                           g_gu + (size_t)e * T_TOK * 2 * MI, 2 * MI,
                           M, 2 * MI, 0, DIM, g_list + e * T_TOK, nullptr, 0);
}
__global__ __launch_bounds__(256, 2) void k_moe_down(const float* __restrict__ ed) {
    int e = blockIdx.z; int M = g_cnt[e];
    gemm_cp<true, 0, true>(g_act + (size_t)e * T_TOK * MI, MI,
                           ed + (size_t)e * DIM * MI, MI,
                           g_down + (size_t)e * T_TOK * DIM, DIM,
                           M, DIM, 0, MI, nullptr, nullptr, 0);
}
__global__ __launch_bounds__(256, 2) void k_gemm_sh(const float* A,
                          const float* B0, const float* B1, float* C0, float* C1) {
    const float* B = blockIdx.z ? B1 : B0;
    float* C = blockIdx.z ? C1 : C0;
    gemm_cp<false, 0, true>(A, DIM, B, SI, C, SI, T_TOK, SI, 0, DIM, nullptr, nullptr, 0);
}
__global__ __launch_bounds__(256, 2) void k_gemm_shd(const float* A, const float* B, float* C) {
    int kz = blockIdx.z;
    gemm_cp<false, 2, true>(A, SI, B, DIM, C, DIM, T_TOK, DIM,
                            kz * 1408, kz * 1408 + 1408, nullptr, nullptr, 0);
}

// ---------------- elementwise / norm / softmax kernels ----------------
__global__ void k_zero_cnt() { if (threadIdx.x < NE) g_cnt[threadIdx.x] = 0; }

__global__ void k_rmsnorm(const float* __restrict__ in, const float* __restrict__ w,
                          float* __restrict__ out_exact, float* __restrict__ out_round) {
    int t = blockIdx.x; int tid = threadIdx.x;
    const float* r = in + (size_t)t * DIM;
    float ss = 0.f;
    for (int d = tid; d < DIM; d += 256) { float v = r[d]; ss += v * v; }
    __shared__ float sm[256];
    sm[tid] = ss; __syncthreads();
    for (int o = 128; o > 0; o >>= 1) { if (tid < o) sm[tid] += sm[tid + o]; __syncthreads(); }
    float rinv = rsqrtf(sm[0] * (1.0f / DIM) + EPS_F);
    for (int d = tid; d < DIM; d += 256) {
        float v = r[d] * rinv * (1.0f + w[d]);
        if (out_exact) out_exact[(size_t)t * DIM + d] = v;
        out_round[(size_t)t * DIM + d] = rnd_tf32(v);
    }
}

// warp-per-head rope: lane holds float4 (4 consecutive d); pairs are lane-local.
__device__ __forceinline__ float4 rope_vec(float4 v, int lane, int pos,
                                           const float* __restrict__ nw,
                                           const float* __restrict__ fc) {
    float ss = v.x * v.x + v.y * v.y + v.z * v.z + v.w * v.w;
#pragma unroll
    for (int o = 16; o > 0; o >>= 1) ss += __shfl_xor_sync(0xffffffffu, ss, o);
    float rinv = rsqrtf(ss * (1.0f / HD) + EPS_F);
    const float4 nwv = *(const float4*)(nw + lane * 4);
    float x0 = v.x * rinv * (1.0f + nwv.x);
    float x1 = v.y * rinv * (1.0f + nwv.y);
    float x2 = v.z * rinv * (1.0f + nwv.z);
    float x3 = v.w * rinv * (1.0f + nwv.w);
    float4 o;
    if (lane < 16) {
        int i0 = lane * 2, i1 = lane * 2 + 1;
        float c0 = fc[((size_t)pos * 32 + i0) * 2 + 0];
        float s0 = fc[((size_t)pos * 32 + i0) * 2 + 1];
        float c1 = fc[((size_t)pos * 32 + i1) * 2 + 0];
        float s1 = fc[((size_t)pos * 32 + i1) * 2 + 1];
        o.x = x0 * c0 - x1 * s0;
        o.y = x0 * s0 + x1 * c0;
        o.z = x2 * c1 - x3 * s1;
        o.w = x2 * s1 + x3 * c1;
    } else { o.x = x0; o.y = x1; o.z = x2; o.w = x3; }
    o.x = rnd_tf32(o.x); o.y = rnd_tf32(o.y); o.z = rnd_tf32(o.z); o.w = rnd_tf32(o.w);
    return o;
}

// tbase: starting token (batch split)
__global__ void k_rope_q(const float* __restrict__ qn, const float* __restrict__ fc,
                         const int* __restrict__ seqpos, int tbase) {
    int idx = blockIdx.x * 8 + (threadIdx.x >> 5);
    int lane = threadIdx.x & 31;
    int t = tbase + (idx >> 5), h = idx & 31;
    int b = t >> 9, s = t & 511;
    float4* base = (float4*)(g_xq + (size_t)t * (NH * 256) + h * 256) + lane;
    float4 v = *base;
    *base = rope_vec(v, lane, seqpos[b] + s, qn, fc);
}

__global__ void k_rope_k(const float* __restrict__ kn, const float* __restrict__ fc,
                         const int* __restrict__ seqpos) {
    int idx = blockIdx.x * 8 + (threadIdx.x >> 5);
    int lane = threadIdx.x & 31;
    int t = idx >> 2, h = idx & 3;
    int b = t >> 9, s = t & 511;
    float4 v = *((const float4*)(g_xk + (size_t)t * (NKV * HD) + h * HD) + lane);
    int pos = seqpos[b] + s;
    float4 o = rope_vec(v, lane, pos, kn, fc);
    *((float4*)(g_ck + (((size_t)(b * NKV + h)) * MC + pos) * HD) + lane) = o;
}

__global__ void k_scatter_v(const int* __restrict__ seqpos) {
    int i = blockIdx.x * 256 + threadIdx.x;
    int t = i >> 7, rem = i & 127;
    int h = rem >> 5, d4 = rem & 31;
    int b = t >> 9, s = t & 511;
    int pos = seqpos[b] + s;
    float4 v = *((const float4*)(g_xv + (size_t)t * (NKV * HD) + h * HD) + d4);
    v.x = rnd_tf32(v.x); v.y = rnd_tf32(v.y); v.z = rnd_tf32(v.z); v.w = rnd_tf32(v.w);
    *((float4*)(g_cv + (((size_t)(b * NKV + h)) * MC + pos) * HD) + d4) = v;
}

__global__ void k_softmax(int b) {
    int q = blockIdx.x; int z = b * 32 + blockIdx.y;
    float* row = g_scores + ((size_t)z * S_LEN + q) * S_LEN;
    int tid = threadIdx.x;
    const float scale = 0.08838834764831845f;
    float vals[4];
    float m = -1e30f;
#pragma unroll
    for (int j = 0; j < 4; j++) {
        int c = tid + j * 128;
        float sv = (c <= q) ? row[c] * scale : -1e30f;
        vals[j] = sv;
        if (sv > m) m = sv;
    }
    __shared__ float red[4];
#pragma unroll
    for (int o = 16; o > 0; o >>= 1) m = fmaxf(m, __shfl_xor_sync(0xffffffffu, m, o));
    if ((tid & 31) == 0) red[tid >> 5] = m;
    __syncthreads();
    m = fmaxf(fmaxf(red[0], red[1]), fmaxf(red[2], red[3]));
    __syncthreads();
    float p[4]; float sum = 0.f;
#pragma unroll
    for (int j = 0; j < 4; j++) {
        int c = tid + j * 128;
        p[j] = (c <= q) ? expf(vals[j] - m) : 0.0f;
        sum += p[j];
    }
#pragma unroll
    for (int o = 16; o > 0; o >>= 1) sum += __shfl_xor_sync(0xffffffffu, sum, o);
    if ((tid & 31) == 0) red[tid >> 5] = sum;
    __syncthreads();
    sum = red[0] + red[1] + red[2] + red[3];
    float inv = 1.0f / sum;
#pragma unroll
    for (int j = 0; j < 4; j++) row[tid + j * 128] = rnd_tf32(p[j] * inv);
}

__global__ void k_router(const float* __restrict__ rw) {
    int t = blockIdx.x; int tid = threadIdx.x;
    float loc[NE];
#pragma unroll
    for (int e = 0; e < NE; e++) loc[e] = 0.f;
    const float* r = g_hf + (size_t)t * DIM;
    for (int d = tid; d < DIM; d += 256) {
        float hv = r[d];
#pragma unroll
        for (int e = 0; e < NE; e++) loc[e] += hv * rw[e * DIM + d];
    }
    __shared__ float sm[256];
    __shared__ float logits[NE];
    for (int e = 0; e < NE; e++) {
        sm[tid] = loc[e]; __syncthreads();
        for (int o = 128; o > 0; o >>= 1) { if (tid < o) sm[tid] += sm[tid + o]; __syncthreads(); }
        if (tid == 0) logits[e] = sm[0];
        __syncthreads();
    }
    if (tid == 0) {
        float mx = logits[0];
        for (int e = 1; e < NE; e++) mx = fmaxf(mx, logits[e]);
        float pe[NE]; float s = 0.f;
        for (int e = 0; e < NE; e++) { pe[e] = expf(logits[e] - mx); s += pe[e]; }
        for (int e = 0; e < NE; e++) pe[e] /= s;
        int i0 = 0; float v0 = pe[0];
        for (int e = 1; e < NE; e++) if (pe[e] > v0) { v0 = pe[e]; i0 = e; }
        int i1 = -1; float v1 = -1.f;
        for (int e = 0; e < NE; e++) if (e != i0 && pe[e] > v1) { v1 = pe[e]; i1 = e; }
        float wsum = v0 + v1;
        float w0 = v0 / wsum, w1 = v1 / wsum;
        int s0 = atomicAdd(&g_cnt[i0], 1); g_list[i0 * T_TOK + s0] = t;
        int s1 = atomicAdd(&g_cnt[i1], 1); g_list[i1 * T_TOK + s1] = t;
        g_texp[t * 2] = i0;  g_tslot[t * 2] = s0;  g_tw[t * 2] = w0;
        g_texp[t * 2 + 1] = i1; g_tslot[t * 2 + 1] = s1; g_tw[t * 2 + 1] = w1;
    }
}

__global__ void k_moe_silu() {
    int e = blockIdx.y;
    int idx = blockIdx.x * 256 + threadIdx.x;
    int rM = g_cnt[e];
    int rr = idx / MI, c = idx - rr * MI;
    if (rr >= rM) return;
    const float* gu = g_gu + ((size_t)e * T_TOK + rr) * 2 * MI;
    float gvv = gu[c], u = gu[MI + c];
    g_act[((size_t)e * T_TOK + rr) * MI + c] = rnd_tf32(gvv / (1.0f + expf(-gvv)) * u);
}

__global__ void k_sh_silu() {
    size_t idx = (size_t)blockIdx.x * 256 + threadIdx.x;
    float gvv = g_shg[idx];
    g_shh[idx] = rnd_tf32(gvv / (1.0f + expf(-gvv)) * g_shu[idx]);
}

__global__ void k_seg(const float* __restrict__ seg) {
    int t = blockIdx.x; int tid = threadIdx.x;
    const float* r = g_hf + (size_t)t * DIM;
    float ss = 0.f;
    for (int d = tid; d < DIM; d += 256) ss += r[d] * seg[d];
    __shared__ float sm[256];
    sm[tid] = ss; __syncthreads();
    for (int o = 128; o > 0; o >>= 1) { if (tid < o) sm[tid] += sm[tid + o]; __syncthreads(); }
    if (tid == 0) g_sg[t] = 1.0f / (1.0f + expf(-sm[0]));
}

__global__ void k_final(const float* __restrict__ x_res, float* __restrict__ out) {
    size_t idx = (size_t)blockIdx.x * 256 + threadIdx.x;
    int t = (int)(idx >> 11);
    int e0 = g_texp[t * 2], e1 = g_texp[t * 2 + 1];
    int s0 = g_tslot[t * 2], s1 = g_tslot[t * 2 + 1];
    int d = (int)(idx & 2047);
    float moe = g_tw[t * 2]     * g_down[((size_t)e0 * T_TOK + s0) * DIM + d]
              + g_tw[t * 2 + 1] * g_down[((size_t)e1 * T_TOK + s1) * DIM + d];
    out[idx] = g_x2[idx] + moe + g_shout[idx] * g_sg[t];
}

// ---------------- launch ----------------
extern "C" void kernel_launch(void* const* d_in, const int* in_sizes, int n_in,
                              void* d_out, int out_size) {
    const float* x    = (const float*)d_in[0];
    const float* fc   = (const float*)d_in[1];
    const float* cin_k = (const float*)d_in[2];
    const float* cin_v = (const float*)d_in[3];
    const int*   seqpos = (const int*)d_in[4];
    const float* wq   = (const float*)d_in[6];
    const float* wk   = (const float*)d_in[7];
    const float* wv   = (const float*)d_in[8];
    const float* wo   = (const float*)d_in[9];
    const float* q_norm = (const float*)d_in[10];
    const float* k_norm = (const float*)d_in[11];
    const float* anw  = (const float*)d_in[12];
    const float* fnw  = (const float*)d_in[13];
    const float* rw   = (const float*)d_in[14];
    const float* egu  = (const float*)d_in[15];
    const float* ed   = (const float*)d_in[16];
    const float* shg  = (const float*)d_in[17];
    const float* shu  = (const float*)d_in[18];
    const float* shd  = (const float*)d_in[19];
    const float* seg  = (const float*)d_in[20];

    float* out = (float*)d_out;
    const size_t OUT_ELEMS = (size_t)2 * S_LEN * DIM;
    const size_t CK_ELEMS  = (size_t)2 * NKV * MC * HD;

    float *p_h, *p_xq, *p_xk, *p_xv, *p_attn, *p_x2, *p_hf, *p_hfr,
          *p_shgb, *p_shub, *p_shhb, *p_shoutb, *p_ck, *p_cv;
    cudaGetSymbolAddress((void**)&p_h,    g_h);
    cudaGetSymbolAddress((void**)&p_xq,   g_xq);
    cudaGetSymbolAddress((void**)&p_xk,   g_xk);
    cudaGetSymbolAddress((void**)&p_xv,   g_xv);
    cudaGetSymbolAddress((void**)&p_attn, g_attn);
    cudaGetSymbolAddress((void**)&p_x2,   g_x2);
    cudaGetSymbolAddress((void**)&p_hf,   g_hf);
    cudaGetSymbolAddress((void**)&p_hfr,  g_hfr);
    cudaGetSymbolAddress((void**)&p_shgb, g_shg);
    cudaGetSymbolAddress((void**)&p_shub, g_shu);
    cudaGetSymbolAddress((void**)&p_shhb, g_shh);
    cudaGetSymbolAddress((void**)&p_shoutb, g_shout);
    cudaGetSymbolAddress((void**)&p_ck,   g_ck);
    cudaGetSymbolAddress((void**)&p_cv,   g_cv);

    static bool init_done = false;
    static cudaStream_t s1, s2;
    static cudaEvent_t ev_fork0, ev_rms1, ev_q0, ev_q1, ev_kvdone,
                       ev_attn0, ev_attn1, ev_rms2, ev_sh, ev_seg, ev_cache;
    if (!init_done) {
        cudaFuncSetAttribute(k_gemm_wq,   cudaFuncAttributeMaxDynamicSharedMemorySize, GEMM_SMEM_BYTES);
        cudaFuncSetAttribute(k_gemm_kv,   cudaFuncAttributeMaxDynamicSharedMemorySize, GEMM_SMEM_BYTES);
        cudaFuncSetAttribute(k_gemm_wo,   cudaFuncAttributeMaxDynamicSharedMemorySize, GEMM_SMEM_BYTES);
        cudaFuncSetAttribute(k_scores,    cudaFuncAttributeMaxDynamicSharedMemorySize, GEMM_SMEM_BYTES);
        cudaFuncSetAttribute(k_attnv,     cudaFuncAttributeMaxDynamicSharedMemorySize, GEMM_SMEM_BYTES);
        cudaFuncSetAttribute(k_moe_gu,    cudaFuncAttributeMaxDynamicSharedMemorySize, GEMM_SMEM_BYTES);
        cudaFuncSetAttribute(k_moe_down,  cudaFuncAttributeMaxDynamicSharedMemorySize, GEMM_SMEM_BYTES);
        cudaFuncSetAttribute(k_gemm_sh,   cudaFuncAttributeMaxDynamicSharedMemorySize, GEMM_SMEM_BYTES);
        cudaFuncSetAttribute(k_gemm_shd,  cudaFuncAttributeMaxDynamicSharedMemorySize, GEMM_SMEM_BYTES);
        cudaStreamCreateWithFlags(&s1, cudaStreamNonBlocking);
        cudaStreamCreateWithFlags(&s2, cudaStreamNonBlocking);
        cudaEventCreateWithFlags(&ev_fork0,  cudaEventDisableTiming);
        cudaEventCreateWithFlags(&ev_rms1,   cudaEventDisableTiming);
        cudaEventCreateWithFlags(&ev_q0,     cudaEventDisableTiming);
        cudaEventCreateWithFlags(&ev_q1,     cudaEventDisableTiming);
        cudaEventCreateWithFlags(&ev_kvdone, cudaEventDisableTiming);
        cudaEventCreateWithFlags(&ev_attn0,  cudaEventDisableTiming);
        cudaEventCreateWithFlags(&ev_attn1,  cudaEventDisableTiming);
        cudaEventCreateWithFlags(&ev_rms2,   cudaEventDisableTiming);
        cudaEventCreateWithFlags(&ev_sh,     cudaEventDisableTiming);
        cudaEventCreateWithFlags(&ev_seg,    cudaEventDisableTiming);
        cudaEventCreateWithFlags(&ev_cache,  cudaEventDisableTiming);
        init_done = true;
    }

    // ---- fork side streams at the start ----
    cudaEventRecord(ev_fork0, 0);
    cudaStreamWaitEvent(s1, ev_fork0, 0);
    cudaStreamWaitEvent(s2, ev_fork0, 0);

    // s1: cache seeds + kv accumulator zeroing
    cudaMemcpyAsync(p_ck, cin_k, CK_ELEMS * sizeof(float), cudaMemcpyDeviceToDevice, s1);
    cudaMemcpyAsync(p_cv, cin_v, CK_ELEMS * sizeof(float), cudaMemcpyDeviceToDevice, s1);
    cudaMemsetAsync(p_xk, 0, (size_t)T_TOK * NKV * HD * sizeof(float), s1);
    cudaMemsetAsync(p_xv, 0, (size_t)T_TOK * NKV * HD * sizeof(float), s1);
    // s2: split-K inits
    cudaMemsetAsync(p_shoutb, 0, (size_t)T_TOK * DIM * sizeof(float), s2);
    cudaMemcpyAsync(p_x2, x, (size_t)T_TOK * DIM * sizeof(float), cudaMemcpyDeviceToDevice, s2);

    // default: rmsnorm1 (+ router counter zero)
    k_zero_cnt<<<1, 32>>>();
    k_rmsnorm<<<T_TOK, 256>>>(x, anw, nullptr, p_h);
    cudaEventRecord(ev_rms1, 0);

    // s1: kv chain (concurrent with wq halves)
    cudaStreamWaitEvent(s1, ev_rms1, 0);
    k_gemm_kv<<<dim3(4, 8, 8), 256, GEMM_SMEM_BYTES, s1>>>(p_h, wk, wv, p_xk, p_xv);
    k_rope_k<<<(T_TOK * NKV) / 8, 256, 0, s1>>>(k_norm, fc, seqpos);
    k_scatter_v<<<(T_TOK * 128) / 256, 256, 0, s1>>>(seqpos);
    cudaEventRecord(ev_kvdone, s1);

    // default: wq batch 0 half -> rope_q(b0)
    k_gemm_wq<<<dim3(64, 4), 256, GEMM_SMEM_BYTES>>>(p_h, wq, p_xq);
    k_rope_q<<<(S_LEN * NH) / 8, 256>>>(q_norm, fc, seqpos, 0);
    cudaEventRecord(ev_q0, 0);

    // s2: attention batch 0 (overlaps wq batch 1 below)
    cudaStreamWaitEvent(s2, ev_q0, 0);
    cudaStreamWaitEvent(s2, ev_kvdone, 0);
    k_scores<<<dim3(4, 4, 32), 256, GEMM_SMEM_BYTES, s2>>>(0);
    k_softmax<<<dim3(S_LEN, 32), 128, 0, s2>>>(0);
    k_attnv<<<dim3(1, 4, 32), 256, GEMM_SMEM_BYTES, s2>>>(0);
    cudaEventRecord(ev_attn0, s2);

    // default: wq batch 1 half -> rope_q(b1)
    k_gemm_wq<<<dim3(64, 4), 256, GEMM_SMEM_BYTES>>>(p_h + (size_t)S_LEN * DIM, wq,
                                                     p_xq + (size_t)S_LEN * (NH * 256));
    k_rope_q<<<(S_LEN * NH) / 8, 256>>>(q_norm, fc, seqpos, S_LEN);
    cudaEventRecord(ev_q1, 0);

    // s1: attention batch 1 (after kv chain in-stream + q1)
    cudaStreamWaitEvent(s1, ev_q1, 0);
    k_scores<<<dim3(4, 4, 32), 256, GEMM_SMEM_BYTES, s1>>>(1);
    k_softmax<<<dim3(S_LEN, 32), 128, 0, s1>>>(1);
    k_attnv<<<dim3(1, 4, 32), 256, GEMM_SMEM_BYTES, s1>>>(1);
    cudaEventRecord(ev_attn1, s1);

    // s2: cache out copies (off critical path)
    cudaStreamWaitEvent(s2, ev_kvdone, 0);
    if ((size_t)out_size >= OUT_ELEMS + 2 * CK_ELEMS) {
        cudaMemcpyAsync(out + OUT_ELEMS, p_ck, CK_ELEMS * sizeof(float),
                        cudaMemcpyDeviceToDevice, s2);
        cudaMemcpyAsync(out + OUT_ELEMS + CK_ELEMS, p_cv, CK_ELEMS * sizeof(float),
                        cudaMemcpyDeviceToDevice, s2);
    }
    cudaEventRecord(ev_cache, s2);

    // default: wo + rmsnorm2 + router
    cudaStreamWaitEvent(0, ev_attn0, 0);
    cudaStreamWaitEvent(0, ev_attn1, 0);
    k_gemm_wo<<<dim3(16, 8, 4), 256, GEMM_SMEM_BYTES>>>(p_attn, wo, p_x2);
    k_rmsnorm<<<T_TOK, 256>>>(p_x2, fnw, p_hf, p_hfr);
    cudaEventRecord(ev_rms2, 0);
    k_router<<<T_TOK, 256>>>(rw);

    // default: MoE chain
    k_moe_gu<<<dim3(22, 8, 8), 256, GEMM_SMEM_BYTES>>>(egu);
    k_moe_silu<<<dim3((T_TOK * MI) / 256, 8), 256>>>();
    k_moe_down<<<dim3(16, 8, 8), 256, GEMM_SMEM_BYTES>>>(ed);

    // s1: shared-expert chain concurrent with MoE
    cudaStreamWaitEvent(s1, ev_rms2, 0);
    k_gemm_sh<<<dim3(44, 8, 2), 256, GEMM_SMEM_BYTES, s1>>>(p_hfr, shg, shu, p_shgb, p_shub);
    k_sh_silu<<<(int)(((size_t)T_TOK * SI) / 256), 256, 0, s1>>>();
    k_gemm_shd<<<dim3(16, 8, 4), 256, GEMM_SMEM_BYTES, s1>>>(p_shhb, shd, p_shoutb);
    cudaEventRecord(ev_sh, s1);

    // s2: seg gate
    cudaStreamWaitEvent(s2, ev_rms2, 0);
    k_seg<<<T_TOK, 256, 0, s2>>>(seg);
    cudaEventRecord(ev_seg, s2);

    // join + final combine
    cudaStreamWaitEvent(0, ev_sh, 0);
    cudaStreamWaitEvent(0, ev_seg, 0);
    cudaStreamWaitEvent(0, ev_cache, 0);
    k_final<<<(T_TOK * DIM) / 256, 256>>>(x, out);
}